// round 15
// baseline (speedup 1.0000x reference)
#include <cuda_runtime.h>
#include <cuda_fp16.h>
#include <math.h>
#include <stdint.h>

// Problem constants (FlashRWLargeAttention_59064390255025)
#define G_   8
#define H_   16
#define D_   64
#define B_   2
#define S_   1024
#define T_   (B_ * S_)            // 2048
#define HID_ (G_ * H_ * D_)       // 8192
#define NQKV (G_ * (H_ + 2) * D_) // 9216
#define CACHE_SLOTS 4096
#define CACHE_ELEMS (2 * CACHE_SLOTS * G_ * D_)
#define OUT_ELEMS ((size_t)T_ * HID_)
#define SCALE_ 0.125f

// Scratch (__device__ globals; no allocs allowed)
__device__ float  g_qkv   [(size_t)T_ * NQKV];     // QKV GEMM out (f32)
__device__ __half g_qh    [(size_t)T_ * HID_];     // rotated Q (half, pre-scaled)
__device__ __half g_kh    [(size_t)T_ * G_ * D_];  // rotated K (half)
__device__ __half g_vh    [(size_t)T_ * G_ * D_];  // V (half)
__device__ __half g_hid_h [(size_t)T_ * HID_];     // hidden in half
__device__ __half g_attn_h[(size_t)T_ * HID_];     // attention out (half)
__device__ __half g_wqkv_t[(size_t)NQKV * HID_];   // w_qkv^T  [N][K] half
__device__ __half g_wdns_t[(size_t)HID_ * HID_];   // w_dense^T [N][K] half

// ---------------------------------------------------------------------------
// helpers
// ---------------------------------------------------------------------------
__device__ __forceinline__ uint32_t smem_u32(const void* p) {
    uint32_t r;
    asm("{ .reg .u64 t; cvta.to.shared.u64 t, %1; cvt.u32.u64 %0, t; }"
        : "=r"(r) : "l"(p));
    return r;
}
__device__ __forceinline__ void cp16(uint32_t dst, const void* src) {
    asm volatile("cp.async.cg.shared.global [%0], [%1], 16;"
                 :: "r"(dst), "l"(src) : "memory");
}
__device__ __forceinline__ void ldm_x4(uint32_t* r, uint32_t addr) {
    asm volatile("ldmatrix.sync.aligned.m8n8.x4.shared.b16 {%0,%1,%2,%3}, [%4];"
                 : "=r"(r[0]), "=r"(r[1]), "=r"(r[2]), "=r"(r[3]) : "r"(addr));
}
__device__ __forceinline__ void ldm_x4t(uint32_t* r, uint32_t addr) {
    asm volatile("ldmatrix.sync.aligned.m8n8.x4.trans.shared.b16 {%0,%1,%2,%3}, [%4];"
                 : "=r"(r[0]), "=r"(r[1]), "=r"(r[2]), "=r"(r[3]) : "r"(addr));
}
__device__ __forceinline__ void mma_f16(float* c, const uint32_t* a,
                                        const uint32_t* b) {
    asm volatile(
        "mma.sync.aligned.m16n8k16.row.col.f32.f16.f16.f32 "
        "{%0,%1,%2,%3}, {%4,%5,%6,%7}, {%8,%9}, {%0,%1,%2,%3};\n"
        : "+f"(c[0]), "+f"(c[1]), "+f"(c[2]), "+f"(c[3])
        : "r"(a[0]), "r"(a[1]), "r"(a[2]), "r"(a[3]), "r"(b[0]), "r"(b[1]));
}
__device__ __forceinline__ uint32_t h2pack(float a, float b) {
    __half2 h = __floats2half2_rn(a, b);
    return *(uint32_t*)&h;
}

// ---------------------------------------------------------------------------
// Pre-convert kernels
// ---------------------------------------------------------------------------
// Transpose v2: 64x64 tiles, 128B coalesced half2 stores.
__global__ __launch_bounds__(256) void cvt_transpose64(
    const float* __restrict__ W, __half* __restrict__ Wt, int K, int N,
    int n_off)
{
    __shared__ float s[64][65];
    const int n0 = (blockIdx.x + n_off) * 64;
    const int k0 = blockIdx.y * 64;
    const int tid = threadIdx.x;
    const int wid = tid >> 5, lane = tid & 31;

#pragma unroll
    for (int i = 0; i < 4; i++) {
        int idx = i * 256 + tid;
        int r = idx >> 4, c4 = idx & 15;
        float4 v = *(const float4*)(W + (size_t)(k0 + r) * N + n0 + c4 * 4);
        s[r][c4 * 4 + 0] = v.x;
        s[r][c4 * 4 + 1] = v.y;
        s[r][c4 * 4 + 2] = v.z;
        s[r][c4 * 4 + 3] = v.w;
    }
    __syncthreads();

#pragma unroll
    for (int it = 0; it < 8; it++) {
        int nr = wid + 8 * it;
        uint32_t h2 = h2pack(s[2 * lane][nr], s[2 * lane + 1][nr]);
        *(uint32_t*)(Wt + (size_t)(n0 + nr) * K + k0 + 2 * lane) = h2;
    }
}

__global__ __launch_bounds__(256) void cvt_half(
    const float* __restrict__ src, __half* __restrict__ dst, size_t n4)
{
    size_t i = (size_t)blockIdx.x * blockDim.x + threadIdx.x;
    for (; i < n4; i += (size_t)gridDim.x * blockDim.x) {
        float4 v = ((const float4*)src)[i];
        __half2 h0 = __floats2half2_rn(v.x, v.y);
        __half2 h1 = __floats2half2_rn(v.z, v.w);
        uint2 o = { *(uint32_t*)&h0, *(uint32_t*)&h1 };
        ((uint2*)dst)[i] = o;
    }
}

// ---------------------------------------------------------------------------
// fp16 HMMA GEMM (R7/R9 config): C[M,N](f32) = A[M,K] @ Wt[N,K]^T + bias
// CTA 128x128x64, 8 warps (2m x 4n), warp tile 64x32, 2 CTAs/SM.
// ---------------------------------------------------------------------------
#define BM 128
#define BN 128
#define BK 64
#define RPADB 144
#define A_BYTES (BM * RPADB)
#define B_BYTES (BN * RPADB)
#define STG_BYTES (A_BYTES + B_BYTES)
#define NSTG 3
#define GEMM_SMEM (NSTG * STG_BYTES)   // 110592

__global__ __launch_bounds__(256, 2) void gemm_f16(
    const __half* __restrict__ A, const __half* __restrict__ Wt,
    const float* __restrict__ bias, float* __restrict__ C,
    int K, int N)
{
    extern __shared__ __align__(128) uint8_t smem[];
    const uint32_t sbase = smem_u32(smem);
    const int tid = threadIdx.x;
    const int wid = tid >> 5, lane = tid & 31;
    const int l4r = lane >> 2, l4c = lane & 3;
    const int wm = (wid >> 2) * 64;
    const int wn = (wid & 3) * 32;
    const int row0 = blockIdx.x * BM;
    const int col0 = blockIdx.y * BN;

    const uint32_t rowA = (lane & 7) + ((lane >> 3) & 1) * 8;
    const uint32_t colA = (lane >> 4) * 16;
    const uint32_t rowB = (lane & 7) + (lane >> 4) * 8;
    const uint32_t colB = ((lane >> 3) & 1) * 16;

    float acc[4][4][4];
#pragma unroll
    for (int mi = 0; mi < 4; mi++)
#pragma unroll
        for (int ni = 0; ni < 4; ni++)
#pragma unroll
            for (int j = 0; j < 4; j++) acc[mi][ni][j] = 0.f;

    const int NT = K / BK;

    auto issue = [&](int kt) {
        const int st = kt % NSTG;
        const uint32_t sA = sbase + st * STG_BYTES;
        const uint32_t sB = sA + A_BYTES;
        const int k0 = kt * BK;
#pragma unroll
        for (int i = 0; i < 4; i++) {
            int idx = i * 256 + tid;
            int m = idx >> 3, c = idx & 7;
            cp16(sA + (uint32_t)(m * RPADB + c * 16),
                 A + (size_t)(row0 + m) * K + k0 + c * 8);
        }
#pragma unroll
        for (int i = 0; i < 4; i++) {
            int idx = i * 256 + tid;
            int n = idx >> 3, c = idx & 7;
            cp16(sB + (uint32_t)(n * RPADB + c * 16),
                 Wt + (size_t)(col0 + n) * K + k0 + c * 8);
        }
        asm volatile("cp.async.commit_group;" ::: "memory");
    };

    issue(0); issue(1);

    for (int kt = 0; kt < NT; kt++) {
        if (kt + 1 < NT) asm volatile("cp.async.wait_group 1;" ::: "memory");
        else             asm volatile("cp.async.wait_group 0;" ::: "memory");
        __syncthreads();

        const int st = kt % NSTG;
        const uint32_t sA = sbase + st * STG_BYTES;
        const uint32_t sB = sA + A_BYTES;

#pragma unroll
        for (int ks = 0; ks < 4; ks++) {
            uint32_t af[4][4];
#pragma unroll
            for (int mi = 0; mi < 4; mi++)
                ldm_x4(af[mi], sA + (wm + mi * 16 + rowA) * RPADB + ks * 32 + colA);
            uint32_t bf[4][2];
#pragma unroll
            for (int nip = 0; nip < 2; nip++) {
                uint32_t r[4];
                ldm_x4(r, sB + (wn + nip * 16 + rowB) * RPADB + ks * 32 + colB);
                bf[2 * nip][0] = r[0]; bf[2 * nip][1] = r[1];
                bf[2 * nip + 1][0] = r[2]; bf[2 * nip + 1][1] = r[3];
            }
#pragma unroll
            for (int mi = 0; mi < 4; mi++)
#pragma unroll
                for (int ni = 0; ni < 4; ni++)
                    mma_f16(acc[mi][ni], af[mi], bf[ni]);
        }
        if (kt + 2 < NT) issue(kt + 2);
    }

#pragma unroll
    for (int mi = 0; mi < 4; mi++) {
        int r = row0 + wm + mi * 16 + l4r;
#pragma unroll
        for (int ni = 0; ni < 4; ni++) {
            int c = col0 + wn + ni * 8 + l4c * 2;
            float b0 = bias[c], b1 = bias[c + 1];
            float2 v0 = { acc[mi][ni][0] + b0, acc[mi][ni][1] + b1 };
            float2 v1 = { acc[mi][ni][2] + b0, acc[mi][ni][3] + b1 };
            *(float2*)(C + (size_t)r * N + c) = v0;
            *(float2*)(C + (size_t)(r + 8) * N + c) = v1;
        }
    }
}

// ---------------------------------------------------------------------------
// Rotary + split + cache scatter; 512 threads (8 groups x 64 dims per token)
// ---------------------------------------------------------------------------
__global__ __launch_bounds__(512) void rotary_split(
    const float* __restrict__ cosp, const float* __restrict__ sinp,
    const int* __restrict__ slots, float* __restrict__ cache_dst)
{
    int t = blockIdx.x;
    int g = threadIdx.x >> 6;
    int d = threadIdx.x & 63;
    int half = d & 31;
    float c = cosp[t * 32 + half];
    float s = sinp[t * 32 + half];

    const float* row = g_qkv + (size_t)t * NQKV + (size_t)(g * (H_ + 2)) * D_;

#pragma unroll 4
    for (int h = 0; h < H_; h++) {
        const float* x = row + h * D_;
        float v0 = x[d], out;
        if (d < 32) { float v1 = x[d + 32]; out = v0 * c - v1 * s; }
        else        { float v1 = x[d - 32]; out = v0 * c + v1 * s; }
        g_qh[(size_t)t * HID_ + (size_t)(g * H_ + h) * D_ + d] =
            __float2half(out * SCALE_);
    }
    float kv_k, kv_v;
    {
        const float* x = row + H_ * D_;
        float v0 = x[d];
        if (d < 32) { float v1 = x[d + 32]; kv_k = v0 * c - v1 * s; }
        else        { float v1 = x[d - 32]; kv_k = v0 * c + v1 * s; }
    }
    kv_v = row[(H_ + 1) * D_ + d];
    g_kh[((size_t)t * G_ + g) * D_ + d] = __float2half(kv_k);
    g_vh[((size_t)t * G_ + g) * D_ + d] = __float2half(kv_v);

    int slot = slots[t];
    size_t kidx = ((size_t)slot * G_ + g) * D_ + d;
    cache_dst[kidx] = kv_k;
    cache_dst[(size_t)CACHE_SLOTS * G_ * D_ + kidx] = kv_v;
}

__global__ void cache_copy(const float* __restrict__ src, float* __restrict__ dst)
{
    size_t i = (size_t)blockIdx.x * blockDim.x + threadIdx.x;
    const float4* s4 = (const float4*)src;
    float4* d4 = (float4*)dst;
    size_t n4 = CACHE_ELEMS / 4;
    for (; i < n4; i += (size_t)gridDim.x * blockDim.x) d4[i] = s4[i];
}

// ---------------------------------------------------------------------------
// Flash attention v4: q-tile 128 (8 warps, 256 threads), double-buffered KV.
// Grid (S/128, B*G*H): qtile on x (varies fastest -> balanced waves).
// ---------------------------------------------------------------------------
#define ATT_RPAD 144
#define ATT_STG (2 * 64 * ATT_RPAD)   // K+V per stage = 18432 B
__global__ __launch_bounds__(256) void attn_fa()
{
    __shared__ __align__(128) uint8_t asm_[2 * ATT_STG];
    const uint32_t sbase = smem_u32(asm_);

    const int task = blockIdx.y;             // (b*G + g)*H + h
    const int h = task % H_;
    const int g = (task / H_) % G_;
    const int b = task / (H_ * G_);
    const int qt0 = blockIdx.x * 128;
    const int tid = threadIdx.x, wid = tid >> 5, lane = tid & 31;
    const int qw0 = qt0 + wid * 16;
    const int l4r = lane >> 2, l4c = lane & 3;

    const uint32_t rowB = (lane & 7) + (lane >> 4) * 8;          // K frags
    const uint32_t colB = ((lane >> 3) & 1) * 16;
    const uint32_t rowV = (lane & 7) + ((lane >> 3) & 1) * 8;    // V frags (trans)
    const uint32_t colV = (lane >> 4) * 16;

    uint32_t qa[4][4];
    {
        const __half* qA = g_qh + (size_t)(b * S_ + qw0 + l4r) * HID_
                         + (size_t)(g * H_ + h) * D_;
        const __half* qB = qA + (size_t)8 * HID_;
#pragma unroll
        for (int kc = 0; kc < 4; kc++) {
            qa[kc][0] = *(const uint32_t*)(qA + kc * 16 + 2 * l4c);
            qa[kc][1] = *(const uint32_t*)(qB + kc * 16 + 2 * l4c);
            qa[kc][2] = *(const uint32_t*)(qA + kc * 16 + 8 + 2 * l4c);
            qa[kc][3] = *(const uint32_t*)(qB + kc * 16 + 8 + 2 * l4c);
        }
    }

    float o[8][4];
#pragma unroll
    for (int ni = 0; ni < 8; ni++)
#pragma unroll
        for (int e = 0; e < 4; e++) o[ni][e] = 0.f;
    float m0 = -INFINITY, m1 = -INFINITY, l0 = 0.f, l1 = 0.f;

    const int ntile = qt0 / 64 + 2;   // covers keys [0, qt0+128)

    auto kvissue = [&](int jt) {
        const uint32_t sK = sbase + (jt & 1) * ATT_STG;
        const uint32_t sV = sK + 64 * ATT_RPAD;
        const int j0 = jt * 64;
        // 64 rows x 8 chunks = 512 chunks, 2 per thread (256 threads)
#pragma unroll
        for (int i = 0; i < 2; i++) {
            int idx = i * 256 + tid;
            int j = idx >> 3, c = idx & 7;
            size_t src = ((size_t)(b * S_ + j0 + j) * G_ + g) * D_ + c * 8;
            cp16(sK + j * ATT_RPAD + c * 16, g_kh + src);
            cp16(sV + j * ATT_RPAD + c * 16, g_vh + src);
        }
        asm volatile("cp.async.commit_group;" ::: "memory");
    };

    kvissue(0);

    for (int jt = 0; jt < ntile; jt++) {
        const int j0 = jt * 64;
        if (jt + 1 < ntile) {
            kvissue(jt + 1);
            asm volatile("cp.async.wait_group 1;" ::: "memory");
        } else {
            asm volatile("cp.async.wait_group 0;" ::: "memory");
        }
        __syncthreads();

        const uint32_t sK = sbase + (jt & 1) * ATT_STG;
        const uint32_t sV = sK + 64 * ATT_RPAD;

        if (j0 <= qw0 + 15) {
            float s[8][4];
#pragma unroll
            for (int ni = 0; ni < 8; ni++)
#pragma unroll
                for (int e = 0; e < 4; e++) s[ni][e] = 0.f;
#pragma unroll
            for (int kc = 0; kc < 4; kc++) {
                uint32_t bk[8][2];
#pragma unroll
                for (int nip = 0; nip < 4; nip++) {
                    uint32_t r[4];
                    ldm_x4(r, sK + (nip * 16 + rowB) * ATT_RPAD + kc * 32 + colB);
                    bk[2 * nip][0] = r[0]; bk[2 * nip][1] = r[1];
                    bk[2 * nip + 1][0] = r[2]; bk[2 * nip + 1][1] = r[3];
                }
#pragma unroll
                for (int ni = 0; ni < 8; ni++)
                    mma_f16(s[ni], qa[kc], bk[ni]);
            }
            if (j0 + 63 > qw0) {
                const int rq0 = qw0 + l4r, rq1 = rq0 + 8;
#pragma unroll
                for (int ni = 0; ni < 8; ni++) {
                    int k0i = j0 + ni * 8 + 2 * l4c;
                    if (k0i > rq0)     s[ni][0] = -1e30f;
                    if (k0i + 1 > rq0) s[ni][1] = -1e30f;
                    if (k0i > rq1)     s[ni][2] = -1e30f;
                    if (k0i + 1 > rq1) s[ni][3] = -1e30f;
                }
            }
            float mx0 = -1e30f, mx1 = -1e30f;
#pragma unroll
            for (int ni = 0; ni < 8; ni++) {
                mx0 = fmaxf(mx0, fmaxf(s[ni][0], s[ni][1]));
                mx1 = fmaxf(mx1, fmaxf(s[ni][2], s[ni][3]));
            }
            mx0 = fmaxf(mx0, __shfl_xor_sync(0xffffffffu, mx0, 1));
            mx0 = fmaxf(mx0, __shfl_xor_sync(0xffffffffu, mx0, 2));
            mx1 = fmaxf(mx1, __shfl_xor_sync(0xffffffffu, mx1, 1));
            mx1 = fmaxf(mx1, __shfl_xor_sync(0xffffffffu, mx1, 2));
            float m0n = fmaxf(m0, mx0), m1n = fmaxf(m1, mx1);
            float sum0 = 0.f, sum1 = 0.f;
#pragma unroll
            for (int ni = 0; ni < 8; ni++) {
                s[ni][0] = __expf(s[ni][0] - m0n);
                s[ni][1] = __expf(s[ni][1] - m0n);
                s[ni][2] = __expf(s[ni][2] - m1n);
                s[ni][3] = __expf(s[ni][3] - m1n);
                sum0 += s[ni][0] + s[ni][1];
                sum1 += s[ni][2] + s[ni][3];
            }
            sum0 += __shfl_xor_sync(0xffffffffu, sum0, 1);
            sum0 += __shfl_xor_sync(0xffffffffu, sum0, 2);
            sum1 += __shfl_xor_sync(0xffffffffu, sum1, 1);
            sum1 += __shfl_xor_sync(0xffffffffu, sum1, 2);
            float c0 = __expf(m0 - m0n), c1 = __expf(m1 - m1n);
            l0 = l0 * c0 + sum0;
            l1 = l1 * c1 + sum1;
            m0 = m0n; m1 = m1n;
#pragma unroll
            for (int ni = 0; ni < 8; ni++) {
                o[ni][0] *= c0; o[ni][1] *= c0;
                o[ni][2] *= c1; o[ni][3] *= c1;
            }
            uint32_t ph[4][4];
#pragma unroll
            for (int kc = 0; kc < 4; kc++) {
                ph[kc][0] = h2pack(s[2 * kc][0], s[2 * kc][1]);
                ph[kc][1] = h2pack(s[2 * kc][2], s[2 * kc][3]);
                ph[kc][2] = h2pack(s[2 * kc + 1][0], s[2 * kc + 1][1]);
                ph[kc][3] = h2pack(s[2 * kc + 1][2], s[2 * kc + 1][3]);
            }
#pragma unroll
            for (int kc = 0; kc < 4; kc++) {
                uint32_t bv[8][2];
#pragma unroll
                for (int nip = 0; nip < 4; nip++) {
                    uint32_t r[4];
                    ldm_x4t(r, sV + (kc * 16 + rowV) * ATT_RPAD + nip * 32 + colV);
                    bv[2 * nip][0] = r[0]; bv[2 * nip][1] = r[1];
                    bv[2 * nip + 1][0] = r[2]; bv[2 * nip + 1][1] = r[3];
                }
#pragma unroll
                for (int ni = 0; ni < 8; ni++)
                    mma_f16(o[ni], ph[kc], bv[ni]);
            }
        }
        __syncthreads();
    }

    float inv0 = 1.f / l0, inv1 = 1.f / l1;
    {
        __half* oA = g_attn_h + (size_t)(b * S_ + qw0 + l4r) * HID_
                   + (size_t)(g * H_ + h) * D_ + 2 * l4c;
        __half* oB = oA + (size_t)8 * HID_;
#pragma unroll
        for (int ni = 0; ni < 8; ni++) {
            uint32_t hA = h2pack(o[ni][0] * inv0, o[ni][1] * inv0);
            uint32_t hB = h2pack(o[ni][2] * inv1, o[ni][3] * inv1);
            *(uint32_t*)(oA + ni * 8) = hA;
            *(uint32_t*)(oB + ni * 8) = hB;
        }
    }
}

// ---------------------------------------------------------------------------
// kernel_launch — R14 structure (split transpose64 + concurrent DRAM phase)
// ---------------------------------------------------------------------------
#define WQ_TILES (NQKV / 64)    // 144
#define WQ_HALF  (WQ_TILES / 2) // 72
extern "C" void kernel_launch(void* const* d_in, const int* in_sizes, int n_in,
                              void* d_out, int out_size)
{
    const float* hidden  = (const float*)d_in[0];
    const float* cosp    = (const float*)d_in[1];
    const float* sinp    = (const float*)d_in[2];
    const float* w_qkv   = (const float*)d_in[3];
    const float* b_qkv   = (const float*)d_in[4];
    const float* w_dense = (const float*)d_in[5];
    const float* b_dense = (const float*)d_in[6];
    const float* kvcache = (const float*)d_in[7];
    const int*   slots   = (const int*)d_in[8];

    float* out       = (float*)d_out;
    float* out_cache = out + OUT_ELEMS;

    float  *p_qkv;
    __half *p_hid, *p_attn, *p_wq, *p_wd;
    cudaGetSymbolAddress((void**)&p_qkv,  g_qkv);
    cudaGetSymbolAddress((void**)&p_hid,  g_hid_h);
    cudaGetSymbolAddress((void**)&p_attn, g_attn_h);
    cudaGetSymbolAddress((void**)&p_wq,   g_wqkv_t);
    cudaGetSymbolAddress((void**)&p_wd,   g_wdns_t);

    static cudaStream_t s2 = nullptr;
    static cudaEvent_t evFork = nullptr, evHid = nullptr, evWq2 = nullptr,
                       evCopy = nullptr, evWd = nullptr;
    if (s2 == nullptr) {
        cudaStreamCreateWithFlags(&s2, cudaStreamNonBlocking);
        cudaEventCreateWithFlags(&evFork, cudaEventDisableTiming);
        cudaEventCreateWithFlags(&evHid,  cudaEventDisableTiming);
        cudaEventCreateWithFlags(&evWq2,  cudaEventDisableTiming);
        cudaEventCreateWithFlags(&evCopy, cudaEventDisableTiming);
        cudaEventCreateWithFlags(&evWd,   cudaEventDisableTiming);
        cudaFuncSetAttribute(gemm_f16,
            cudaFuncAttributeMaxDynamicSharedMemorySize, GEMM_SMEM);
    }

    // fork side stream
    cudaEventRecord(evFork, 0);
    cudaStreamWaitEvent(s2, evFork, 0);

    // s2: hidden->half, w_qkv transpose half 2, cache copy, w_dense transpose
    cvt_half<<<1024, 256, 0, s2>>>(hidden, p_hid, OUT_ELEMS / 4);
    cudaEventRecord(evHid, s2);
    cvt_transpose64<<<dim3(WQ_HALF, HID_ / 64), 256, 0, s2>>>(
        w_qkv, p_wq, HID_, NQKV, WQ_HALF);
    cudaEventRecord(evWq2, s2);
    cache_copy<<<4096, 256, 0, s2>>>(kvcache, out_cache);
    cudaEventRecord(evCopy, s2);
    cvt_transpose64<<<dim3(HID_ / 64, HID_ / 64), 256, 0, s2>>>(
        w_dense, p_wd, HID_, HID_, 0);
    cudaEventRecord(evWd, s2);

    // main: w_qkv transpose half 1 (concurrent with s2), then QKV GEMM
    cvt_transpose64<<<dim3(WQ_HALF, HID_ / 64), 256>>>(
        w_qkv, p_wq, HID_, NQKV, 0);
    cudaStreamWaitEvent(0, evHid, 0);
    cudaStreamWaitEvent(0, evWq2, 0);
    gemm_f16<<<dim3(T_ / BM, NQKV / BN), 256, GEMM_SMEM>>>(
        p_hid, p_wq, b_qkv, p_qkv, HID_, NQKV);

    // rotary scatter must follow cache_copy
    cudaStreamWaitEvent(0, evCopy, 0);
    rotary_split<<<T_, 512>>>(cosp, sinp, slots, out_cache);

    // attention (q-tile 128, balanced grid order)
    attn_fa<<<dim3(S_ / 128, B_ * G_ * H_), 256>>>();

    // dense GEMM (needs converted w_dense)
    cudaStreamWaitEvent(0, evWd, 0);
    gemm_f16<<<dim3(T_ / BM, HID_ / BN), 256, GEMM_SMEM>>>(
        p_attn, p_wd, b_dense, out, HID_, HID_);
}

// round 17
// speedup vs baseline: 1.0071x; 1.0071x over previous
#include <cuda_runtime.h>
#include <cuda_fp16.h>
#include <math.h>
#include <stdint.h>

// Problem constants (FlashRWLargeAttention_59064390255025)
#define G_   8
#define H_   16
#define D_   64
#define B_   2
#define S_   1024
#define T_   (B_ * S_)            // 2048
#define HID_ (G_ * H_ * D_)       // 8192
#define NQKV (G_ * (H_ + 2) * D_) // 9216
#define CACHE_SLOTS 4096
#define CACHE_ELEMS (2 * CACHE_SLOTS * G_ * D_)
#define OUT_ELEMS ((size_t)T_ * HID_)
#define SCALE_ 0.125f

// Scratch (__device__ globals; no allocs allowed)
__device__ __half g_qkv_h [(size_t)T_ * NQKV];     // QKV GEMM out (half)
__device__ __half g_qh    [(size_t)T_ * HID_];     // rotated Q (half, pre-scaled)
__device__ __half g_kh    [(size_t)T_ * G_ * D_];  // rotated K (half)
__device__ __half g_vh    [(size_t)T_ * G_ * D_];  // V (half)
__device__ __half g_hid_h [(size_t)T_ * HID_];     // hidden in half
__device__ __half g_attn_h[(size_t)T_ * HID_];     // attention out (half)
__device__ __half g_wqkv_t[(size_t)NQKV * HID_];   // w_qkv^T  [N][K] half
__device__ __half g_wdns_t[(size_t)HID_ * HID_];   // w_dense^T [N][K] half

// ---------------------------------------------------------------------------
// helpers
// ---------------------------------------------------------------------------
__device__ __forceinline__ uint32_t smem_u32(const void* p) {
    uint32_t r;
    asm("{ .reg .u64 t; cvta.to.shared.u64 t, %1; cvt.u32.u64 %0, t; }"
        : "=r"(r) : "l"(p));
    return r;
}
__device__ __forceinline__ void cp16(uint32_t dst, const void* src) {
    asm volatile("cp.async.cg.shared.global [%0], [%1], 16;"
                 :: "r"(dst), "l"(src) : "memory");
}
__device__ __forceinline__ void ldm_x4(uint32_t* r, uint32_t addr) {
    asm volatile("ldmatrix.sync.aligned.m8n8.x4.shared.b16 {%0,%1,%2,%3}, [%4];"
                 : "=r"(r[0]), "=r"(r[1]), "=r"(r[2]), "=r"(r[3]) : "r"(addr));
}
__device__ __forceinline__ void ldm_x4t(uint32_t* r, uint32_t addr) {
    asm volatile("ldmatrix.sync.aligned.m8n8.x4.trans.shared.b16 {%0,%1,%2,%3}, [%4];"
                 : "=r"(r[0]), "=r"(r[1]), "=r"(r[2]), "=r"(r[3]) : "r"(addr));
}
__device__ __forceinline__ void mma_f16(float* c, const uint32_t* a,
                                        const uint32_t* b) {
    asm volatile(
        "mma.sync.aligned.m16n8k16.row.col.f32.f16.f16.f32 "
        "{%0,%1,%2,%3}, {%4,%5,%6,%7}, {%8,%9}, {%0,%1,%2,%3};\n"
        : "+f"(c[0]), "+f"(c[1]), "+f"(c[2]), "+f"(c[3])
        : "r"(a[0]), "r"(a[1]), "r"(a[2]), "r"(a[3]), "r"(b[0]), "r"(b[1]));
}
__device__ __forceinline__ uint32_t h2pack(float a, float b) {
    __half2 h = __floats2half2_rn(a, b);
    return *(uint32_t*)&h;
}

// ---------------------------------------------------------------------------
// Pre-convert kernels
// ---------------------------------------------------------------------------
// Transpose v2: 64x64 tiles, 128B coalesced half2 stores.
__global__ __launch_bounds__(256) void cvt_transpose64(
    const float* __restrict__ W, __half* __restrict__ Wt, int K, int N,
    int n_off)
{
    __shared__ float s[64][65];
    const int n0 = (blockIdx.x + n_off) * 64;
    const int k0 = blockIdx.y * 64;
    const int tid = threadIdx.x;
    const int wid = tid >> 5, lane = tid & 31;

#pragma unroll
    for (int i = 0; i < 4; i++) {
        int idx = i * 256 + tid;
        int r = idx >> 4, c4 = idx & 15;
        float4 v = *(const float4*)(W + (size_t)(k0 + r) * N + n0 + c4 * 4);
        s[r][c4 * 4 + 0] = v.x;
        s[r][c4 * 4 + 1] = v.y;
        s[r][c4 * 4 + 2] = v.z;
        s[r][c4 * 4 + 3] = v.w;
    }
    __syncthreads();

#pragma unroll
    for (int it = 0; it < 8; it++) {
        int nr = wid + 8 * it;
        uint32_t h2 = h2pack(s[2 * lane][nr], s[2 * lane + 1][nr]);
        *(uint32_t*)(Wt + (size_t)(n0 + nr) * K + k0 + 2 * lane) = h2;
    }
}

__global__ __launch_bounds__(256) void cvt_half(
    const float* __restrict__ src, __half* __restrict__ dst, size_t n4)
{
    size_t i = (size_t)blockIdx.x * blockDim.x + threadIdx.x;
    for (; i < n4; i += (size_t)gridDim.x * blockDim.x) {
        float4 v = ((const float4*)src)[i];
        __half2 h0 = __floats2half2_rn(v.x, v.y);
        __half2 h1 = __floats2half2_rn(v.z, v.w);
        uint2 o = { *(uint32_t*)&h0, *(uint32_t*)&h1 };
        ((uint2*)dst)[i] = o;
    }
}

// ---------------------------------------------------------------------------
// fp16 HMMA GEMM core (R7/R9 config). Two epilogues: f32 out / half out.
// CTA 128x128x64, 8 warps (2m x 4n), warp tile 64x32, 2 CTAs/SM.
// ---------------------------------------------------------------------------
#define BM 128
#define BN 128
#define BK 64
#define RPADB 144
#define A_BYTES (BM * RPADB)
#define B_BYTES (BN * RPADB)
#define STG_BYTES (A_BYTES + B_BYTES)
#define NSTG 3
#define GEMM_SMEM (NSTG * STG_BYTES)   // 110592

// variadic: epilogue may contain top-level commas
#define GEMM_BODY(...)                                                        \
    extern __shared__ __align__(128) uint8_t smem[];                          \
    const uint32_t sbase = smem_u32(smem);                                    \
    const int tid = threadIdx.x;                                              \
    const int wid = tid >> 5, lane = tid & 31;                                \
    const int l4r = lane >> 2, l4c = lane & 3;                                \
    const int wm = (wid >> 2) * 64;                                           \
    const int wn = (wid & 3) * 32;                                            \
    const int row0 = blockIdx.x * BM;                                         \
    const int col0 = blockIdx.y * BN;                                         \
    const uint32_t rowA = (lane & 7) + ((lane >> 3) & 1) * 8;                 \
    const uint32_t colA = (lane >> 4) * 16;                                   \
    const uint32_t rowB = (lane & 7) + (lane >> 4) * 8;                       \
    const uint32_t colB = ((lane >> 3) & 1) * 16;                             \
    float acc[4][4][4];                                                       \
    _Pragma("unroll")                                                         \
    for (int mi = 0; mi < 4; mi++)                                            \
        _Pragma("unroll")                                                     \
        for (int ni = 0; ni < 4; ni++)                                        \
            _Pragma("unroll")                                                 \
            for (int j = 0; j < 4; j++) acc[mi][ni][j] = 0.f;                 \
    const int NT = K / BK;                                                    \
    auto issue = [&](int kt) {                                                \
        const int st = kt % NSTG;                                             \
        const uint32_t sA = sbase + st * STG_BYTES;                           \
        const uint32_t sB = sA + A_BYTES;                                     \
        const int k0 = kt * BK;                                               \
        _Pragma("unroll")                                                     \
        for (int i = 0; i < 4; i++) {                                         \
            int idx = i * 256 + tid;                                          \
            int m = idx >> 3, c = idx & 7;                                    \
            cp16(sA + (uint32_t)(m * RPADB + c * 16),                         \
                 A + (size_t)(row0 + m) * K + k0 + c * 8);                    \
        }                                                                     \
        _Pragma("unroll")                                                     \
        for (int i = 0; i < 4; i++) {                                         \
            int idx = i * 256 + tid;                                          \
            int n = idx >> 3, c = idx & 7;                                    \
            cp16(sB + (uint32_t)(n * RPADB + c * 16),                         \
                 Wt + (size_t)(col0 + n) * K + k0 + c * 8);                   \
        }                                                                     \
        asm volatile("cp.async.commit_group;" ::: "memory");                  \
    };                                                                        \
    issue(0); issue(1);                                                       \
    for (int kt = 0; kt < NT; kt++) {                                         \
        if (kt + 1 < NT) asm volatile("cp.async.wait_group 1;" ::: "memory"); \
        else             asm volatile("cp.async.wait_group 0;" ::: "memory"); \
        __syncthreads();                                                      \
        const int st = kt % NSTG;                                             \
        const uint32_t sA = sbase + st * STG_BYTES;                           \
        const uint32_t sB = sA + A_BYTES;                                     \
        _Pragma("unroll")                                                     \
        for (int ks = 0; ks < 4; ks++) {                                      \
            uint32_t af[4][4];                                                \
            _Pragma("unroll")                                                 \
            for (int mi = 0; mi < 4; mi++)                                    \
                ldm_x4(af[mi], sA + (wm + mi * 16 + rowA) * RPADB             \
                               + ks * 32 + colA);                             \
            uint32_t bf[4][2];                                                \
            _Pragma("unroll")                                                 \
            for (int nip = 0; nip < 2; nip++) {                               \
                uint32_t r[4];                                                \
                ldm_x4(r, sB + (wn + nip * 16 + rowB) * RPADB                 \
                          + ks * 32 + colB);                                  \
                bf[2 * nip][0] = r[0]; bf[2 * nip][1] = r[1];                 \
                bf[2 * nip + 1][0] = r[2]; bf[2 * nip + 1][1] = r[3];         \
            }                                                                 \
            _Pragma("unroll")                                                 \
            for (int mi = 0; mi < 4; mi++)                                    \
                _Pragma("unroll")                                             \
                for (int ni = 0; ni < 4; ni++)                                \
                    mma_f16(acc[mi][ni], af[mi], bf[ni]);                     \
        }                                                                     \
        if (kt + 2 < NT) issue(kt + 2);                                       \
    }                                                                         \
    __VA_ARGS__

__global__ __launch_bounds__(256, 2) void gemm_f16(
    const __half* __restrict__ A, const __half* __restrict__ Wt,
    const float* __restrict__ bias, float* __restrict__ C,
    int K, int N)
{
    GEMM_BODY(
#pragma unroll
        for (int mi = 0; mi < 4; mi++) {
            int r = row0 + wm + mi * 16 + l4r;
#pragma unroll
            for (int ni = 0; ni < 4; ni++) {
                int c = col0 + wn + ni * 8 + l4c * 2;
                float b0 = bias[c];
                float b1 = bias[c + 1];
                float2 v0;
                v0.x = acc[mi][ni][0] + b0;
                v0.y = acc[mi][ni][1] + b1;
                float2 v1;
                v1.x = acc[mi][ni][2] + b0;
                v1.y = acc[mi][ni][3] + b1;
                *(float2*)(C + (size_t)r * N + c) = v0;
                *(float2*)(C + (size_t)(r + 8) * N + c) = v1;
            }
        }
    )
}

__global__ __launch_bounds__(256, 2) void gemm_f16h(
    const __half* __restrict__ A, const __half* __restrict__ Wt,
    const float* __restrict__ bias, __half* __restrict__ C,
    int K, int N)
{
    GEMM_BODY(
#pragma unroll
        for (int mi = 0; mi < 4; mi++) {
            int r = row0 + wm + mi * 16 + l4r;
#pragma unroll
            for (int ni = 0; ni < 4; ni++) {
                int c = col0 + wn + ni * 8 + l4c * 2;
                float b0 = bias[c];
                float b1 = bias[c + 1];
                uint32_t h0 = h2pack(acc[mi][ni][0] + b0, acc[mi][ni][1] + b1);
                uint32_t h1 = h2pack(acc[mi][ni][2] + b0, acc[mi][ni][3] + b1);
                *(uint32_t*)(C + (size_t)r * N + c) = h0;
                *(uint32_t*)(C + (size_t)(r + 8) * N + c) = h1;
            }
        }
    )
}

// ---------------------------------------------------------------------------
// Rotary + split + cache scatter; reads half qkv; 512 threads per token
// ---------------------------------------------------------------------------
__global__ __launch_bounds__(512) void rotary_split(
    const float* __restrict__ cosp, const float* __restrict__ sinp,
    const int* __restrict__ slots, float* __restrict__ cache_dst)
{
    int t = blockIdx.x;
    int g = threadIdx.x >> 6;
    int d = threadIdx.x & 63;
    int half = d & 31;
    float c = cosp[t * 32 + half];
    float s = sinp[t * 32 + half];

    const __half* row = g_qkv_h + (size_t)t * NQKV + (size_t)(g * (H_ + 2)) * D_;

#pragma unroll 4
    for (int h = 0; h < H_; h++) {
        const __half* x = row + h * D_;
        float v0 = __half2float(x[d]), out;
        if (d < 32) { float v1 = __half2float(x[d + 32]); out = v0 * c - v1 * s; }
        else        { float v1 = __half2float(x[d - 32]); out = v0 * c + v1 * s; }
        g_qh[(size_t)t * HID_ + (size_t)(g * H_ + h) * D_ + d] =
            __float2half(out * SCALE_);
    }
    float kv_k, kv_v;
    {
        const __half* x = row + H_ * D_;
        float v0 = __half2float(x[d]);
        if (d < 32) { float v1 = __half2float(x[d + 32]); kv_k = v0 * c - v1 * s; }
        else        { float v1 = __half2float(x[d - 32]); kv_k = v0 * c + v1 * s; }
    }
    kv_v = __half2float(row[(H_ + 1) * D_ + d]);
    g_kh[((size_t)t * G_ + g) * D_ + d] = __float2half(kv_k);
    g_vh[((size_t)t * G_ + g) * D_ + d] = __float2half(kv_v);

    int slot = slots[t];
    size_t kidx = ((size_t)slot * G_ + g) * D_ + d;
    cache_dst[kidx] = kv_k;
    cache_dst[(size_t)CACHE_SLOTS * G_ * D_ + kidx] = kv_v;
}

__global__ void cache_copy(const float* __restrict__ src, float* __restrict__ dst)
{
    size_t i = (size_t)blockIdx.x * blockDim.x + threadIdx.x;
    const float4* s4 = (const float4*)src;
    float4* d4 = (float4*)dst;
    size_t n4 = CACHE_ELEMS / 4;
    for (; i < n4; i += (size_t)gridDim.x * blockDim.x) d4[i] = s4[i];
}

// ---------------------------------------------------------------------------
// Flash attention (R14 version): q-tile 64, 128 threads, double-buffered KV.
// Grid (B*G*H, S/64).
// ---------------------------------------------------------------------------
#define ATT_RPAD 144
#define ATT_STG (2 * 64 * ATT_RPAD)
__global__ __launch_bounds__(128) void attn_fa()
{
    __shared__ __align__(128) uint8_t asm_[2 * ATT_STG];
    const uint32_t sbase = smem_u32(asm_);

    const int task = blockIdx.x;
    const int h = task % H_;
    const int g = (task / H_) % G_;
    const int b = task / (H_ * G_);
    const int qt0 = blockIdx.y * 64;
    const int tid = threadIdx.x, wid = tid >> 5, lane = tid & 31;
    const int qw0 = qt0 + wid * 16;
    const int l4r = lane >> 2, l4c = lane & 3;

    const uint32_t rowB = (lane & 7) + (lane >> 4) * 8;
    const uint32_t colB = ((lane >> 3) & 1) * 16;
    const uint32_t rowV = (lane & 7) + ((lane >> 3) & 1) * 8;
    const uint32_t colV = (lane >> 4) * 16;

    uint32_t qa[4][4];
    {
        const __half* qA = g_qh + (size_t)(b * S_ + qw0 + l4r) * HID_
                         + (size_t)(g * H_ + h) * D_;
        const __half* qB = qA + (size_t)8 * HID_;
#pragma unroll
        for (int kc = 0; kc < 4; kc++) {
            qa[kc][0] = *(const uint32_t*)(qA + kc * 16 + 2 * l4c);
            qa[kc][1] = *(const uint32_t*)(qB + kc * 16 + 2 * l4c);
            qa[kc][2] = *(const uint32_t*)(qA + kc * 16 + 8 + 2 * l4c);
            qa[kc][3] = *(const uint32_t*)(qB + kc * 16 + 8 + 2 * l4c);
        }
    }

    float o[8][4];
#pragma unroll
    for (int ni = 0; ni < 8; ni++)
#pragma unroll
        for (int e = 0; e < 4; e++) o[ni][e] = 0.f;
    float m0 = -INFINITY, m1 = -INFINITY, l0 = 0.f, l1 = 0.f;

    const int ntile = qt0 / 64 + 1;

    auto kvissue = [&](int jt) {
        const uint32_t sK = sbase + (jt & 1) * ATT_STG;
        const uint32_t sV = sK + 64 * ATT_RPAD;
        const int j0 = jt * 64;
#pragma unroll
        for (int i = 0; i < 4; i++) {
            int idx = i * 128 + tid;
            int j = idx >> 3, c = idx & 7;
            size_t src = ((size_t)(b * S_ + j0 + j) * G_ + g) * D_ + c * 8;
            cp16(sK + j * ATT_RPAD + c * 16, g_kh + src);
            cp16(sV + j * ATT_RPAD + c * 16, g_vh + src);
        }
        asm volatile("cp.async.commit_group;" ::: "memory");
    };

    kvissue(0);

    for (int jt = 0; jt < ntile; jt++) {
        const int j0 = jt * 64;
        if (jt + 1 < ntile) {
            kvissue(jt + 1);
            asm volatile("cp.async.wait_group 1;" ::: "memory");
        } else {
            asm volatile("cp.async.wait_group 0;" ::: "memory");
        }
        __syncthreads();

        const uint32_t sK = sbase + (jt & 1) * ATT_STG;
        const uint32_t sV = sK + 64 * ATT_RPAD;

        if (j0 <= qw0 + 15) {
            float s[8][4];
#pragma unroll
            for (int ni = 0; ni < 8; ni++)
#pragma unroll
                for (int e = 0; e < 4; e++) s[ni][e] = 0.f;
#pragma unroll
            for (int kc = 0; kc < 4; kc++) {
                uint32_t bk[8][2];
#pragma unroll
                for (int nip = 0; nip < 4; nip++) {
                    uint32_t r[4];
                    ldm_x4(r, sK + (nip * 16 + rowB) * ATT_RPAD + kc * 32 + colB);
                    bk[2 * nip][0] = r[0]; bk[2 * nip][1] = r[1];
                    bk[2 * nip + 1][0] = r[2]; bk[2 * nip + 1][1] = r[3];
                }
#pragma unroll
                for (int ni = 0; ni < 8; ni++)
                    mma_f16(s[ni], qa[kc], bk[ni]);
            }
            if (j0 + 63 > qw0) {
                const int rq0 = qw0 + l4r, rq1 = rq0 + 8;
#pragma unroll
                for (int ni = 0; ni < 8; ni++) {
                    int k0i = j0 + ni * 8 + 2 * l4c;
                    if (k0i > rq0)     s[ni][0] = -1e30f;
                    if (k0i + 1 > rq0) s[ni][1] = -1e30f;
                    if (k0i > rq1)     s[ni][2] = -1e30f;
                    if (k0i + 1 > rq1) s[ni][3] = -1e30f;
                }
            }
            float mx0 = -1e30f, mx1 = -1e30f;
#pragma unroll
            for (int ni = 0; ni < 8; ni++) {
                mx0 = fmaxf(mx0, fmaxf(s[ni][0], s[ni][1]));
                mx1 = fmaxf(mx1, fmaxf(s[ni][2], s[ni][3]));
            }
            mx0 = fmaxf(mx0, __shfl_xor_sync(0xffffffffu, mx0, 1));
            mx0 = fmaxf(mx0, __shfl_xor_sync(0xffffffffu, mx0, 2));
            mx1 = fmaxf(mx1, __shfl_xor_sync(0xffffffffu, mx1, 1));
            mx1 = fmaxf(mx1, __shfl_xor_sync(0xffffffffu, mx1, 2));
            float m0n = fmaxf(m0, mx0), m1n = fmaxf(m1, mx1);
            float sum0 = 0.f, sum1 = 0.f;
#pragma unroll
            for (int ni = 0; ni < 8; ni++) {
                s[ni][0] = __expf(s[ni][0] - m0n);
                s[ni][1] = __expf(s[ni][1] - m0n);
                s[ni][2] = __expf(s[ni][2] - m1n);
                s[ni][3] = __expf(s[ni][3] - m1n);
                sum0 += s[ni][0] + s[ni][1];
                sum1 += s[ni][2] + s[ni][3];
            }
            sum0 += __shfl_xor_sync(0xffffffffu, sum0, 1);
            sum0 += __shfl_xor_sync(0xffffffffu, sum0, 2);
            sum1 += __shfl_xor_sync(0xffffffffu, sum1, 1);
            sum1 += __shfl_xor_sync(0xffffffffu, sum1, 2);
            float c0 = __expf(m0 - m0n), c1 = __expf(m1 - m1n);
            l0 = l0 * c0 + sum0;
            l1 = l1 * c1 + sum1;
            m0 = m0n; m1 = m1n;
#pragma unroll
            for (int ni = 0; ni < 8; ni++) {
                o[ni][0] *= c0; o[ni][1] *= c0;
                o[ni][2] *= c1; o[ni][3] *= c1;
            }
            uint32_t ph[4][4];
#pragma unroll
            for (int kc = 0; kc < 4; kc++) {
                ph[kc][0] = h2pack(s[2 * kc][0], s[2 * kc][1]);
                ph[kc][1] = h2pack(s[2 * kc][2], s[2 * kc][3]);
                ph[kc][2] = h2pack(s[2 * kc + 1][0], s[2 * kc + 1][1]);
                ph[kc][3] = h2pack(s[2 * kc + 1][2], s[2 * kc + 1][3]);
            }
#pragma unroll
            for (int kc = 0; kc < 4; kc++) {
                uint32_t bv[8][2];
#pragma unroll
                for (int nip = 0; nip < 4; nip++) {
                    uint32_t r[4];
                    ldm_x4t(r, sV + (kc * 16 + rowV) * ATT_RPAD + nip * 32 + colV);
                    bv[2 * nip][0] = r[0]; bv[2 * nip][1] = r[1];
                    bv[2 * nip + 1][0] = r[2]; bv[2 * nip + 1][1] = r[3];
                }
#pragma unroll
                for (int ni = 0; ni < 8; ni++)
                    mma_f16(o[ni], ph[kc], bv[ni]);
            }
        }
        __syncthreads();
    }

    float inv0 = 1.f / l0, inv1 = 1.f / l1;
    {
        __half* oA = g_attn_h + (size_t)(b * S_ + qw0 + l4r) * HID_
                   + (size_t)(g * H_ + h) * D_ + 2 * l4c;
        __half* oB = oA + (size_t)8 * HID_;
#pragma unroll
        for (int ni = 0; ni < 8; ni++) {
            uint32_t hA = h2pack(o[ni][0] * inv0, o[ni][1] * inv0);
            uint32_t hB = h2pack(o[ni][2] * inv1, o[ni][3] * inv1);
            *(uint32_t*)(oA + ni * 8) = hA;
            *(uint32_t*)(oB + ni * 8) = hB;
        }
    }
}

// ---------------------------------------------------------------------------
// kernel_launch — R14 structure; GEMM1 emits half, rotary reads half.
// ---------------------------------------------------------------------------
#define WQ_TILES (NQKV / 64)    // 144
#define WQ_HALF  (WQ_TILES / 2) // 72
extern "C" void kernel_launch(void* const* d_in, const int* in_sizes, int n_in,
                              void* d_out, int out_size)
{
    const float* hidden  = (const float*)d_in[0];
    const float* cosp    = (const float*)d_in[1];
    const float* sinp    = (const float*)d_in[2];
    const float* w_qkv   = (const float*)d_in[3];
    const float* b_qkv   = (const float*)d_in[4];
    const float* w_dense = (const float*)d_in[5];
    const float* b_dense = (const float*)d_in[6];
    const float* kvcache = (const float*)d_in[7];
    const int*   slots   = (const int*)d_in[8];

    float* out       = (float*)d_out;
    float* out_cache = out + OUT_ELEMS;

    __half *p_qkvh, *p_hid, *p_attn, *p_wq, *p_wd;
    cudaGetSymbolAddress((void**)&p_qkvh, g_qkv_h);
    cudaGetSymbolAddress((void**)&p_hid,  g_hid_h);
    cudaGetSymbolAddress((void**)&p_attn, g_attn_h);
    cudaGetSymbolAddress((void**)&p_wq,   g_wqkv_t);
    cudaGetSymbolAddress((void**)&p_wd,   g_wdns_t);

    static cudaStream_t s2 = nullptr;
    static cudaEvent_t evFork = nullptr, evHid = nullptr, evWq2 = nullptr,
                       evCopy = nullptr, evWd = nullptr;
    if (s2 == nullptr) {
        cudaStreamCreateWithFlags(&s2, cudaStreamNonBlocking);
        cudaEventCreateWithFlags(&evFork, cudaEventDisableTiming);
        cudaEventCreateWithFlags(&evHid,  cudaEventDisableTiming);
        cudaEventCreateWithFlags(&evWq2,  cudaEventDisableTiming);
        cudaEventCreateWithFlags(&evCopy, cudaEventDisableTiming);
        cudaEventCreateWithFlags(&evWd,   cudaEventDisableTiming);
        cudaFuncSetAttribute(gemm_f16,
            cudaFuncAttributeMaxDynamicSharedMemorySize, GEMM_SMEM);
        cudaFuncSetAttribute(gemm_f16h,
            cudaFuncAttributeMaxDynamicSharedMemorySize, GEMM_SMEM);
    }

    // fork side stream
    cudaEventRecord(evFork, 0);
    cudaStreamWaitEvent(s2, evFork, 0);

    // s2: hidden->half, w_qkv transpose half 2, cache copy, w_dense transpose
    cvt_half<<<1024, 256, 0, s2>>>(hidden, p_hid, OUT_ELEMS / 4);
    cudaEventRecord(evHid, s2);
    cvt_transpose64<<<dim3(WQ_HALF, HID_ / 64), 256, 0, s2>>>(
        w_qkv, p_wq, HID_, NQKV, WQ_HALF);
    cudaEventRecord(evWq2, s2);
    cache_copy<<<4096, 256, 0, s2>>>(kvcache, out_cache);
    cudaEventRecord(evCopy, s2);
    cvt_transpose64<<<dim3(HID_ / 64, HID_ / 64), 256, 0, s2>>>(
        w_dense, p_wd, HID_, HID_, 0);
    cudaEventRecord(evWd, s2);

    // main: w_qkv transpose half 1 (concurrent with s2), then QKV GEMM (half out)
    cvt_transpose64<<<dim3(WQ_HALF, HID_ / 64), 256>>>(
        w_qkv, p_wq, HID_, NQKV, 0);
    cudaStreamWaitEvent(0, evHid, 0);
    cudaStreamWaitEvent(0, evWq2, 0);
    gemm_f16h<<<dim3(T_ / BM, NQKV / BN), 256, GEMM_SMEM>>>(
        p_hid, p_wq, b_qkv, p_qkvh, HID_, NQKV);

    // rotary scatter must follow cache_copy
    cudaStreamWaitEvent(0, evCopy, 0);
    rotary_split<<<T_, 512>>>(cosp, sinp, slots, out_cache);

    // attention (R14 config)
    attn_fa<<<dim3(B_ * G_ * H_, S_ / 64), 128>>>();

    // dense GEMM (needs converted w_dense)
    cudaStreamWaitEvent(0, evWd, 0);
    gemm_f16<<<dim3(T_ / BM, HID_ / BN), 256, GEMM_SMEM>>>(
        p_attn, p_wd, b_dense, out, HID_, HID_);
}